// round 1
// baseline (speedup 1.0000x reference)
#include <cuda_runtime.h>

// Problem constants
#define Bb 4096
#define Tt 128
#define Ff 64
#define Hh 32
#define Gg 128   // 4*H

// Scratch (device globals: allocation-free rule)
__device__ float g_xz[(size_t)Bb * Tt * Gg];   // 268 MB: x@We + be, laid out [b*T+t][128]
__device__ float g_hT[Bb * Hh];                // encoder final hidden

typedef unsigned long long u64;

// ---------- f32x2 packed helpers (Blackwell sm_100+) ----------
__device__ __forceinline__ u64 pk2(float lo, float hi) {
    u64 r; asm("mov.b64 %0, {%1, %2};" : "=l"(r) : "f"(lo), "f"(hi)); return r;
}
__device__ __forceinline__ void upk2(u64 v, float &lo, float &hi) {
    asm("mov.b64 {%0, %1}, %2;" : "=f"(lo), "=f"(hi) : "l"(v));
}
__device__ __forceinline__ u64 f2u(float2 v) { return pk2(v.x, v.y); }
__device__ __forceinline__ u64 fma2(u64 a, u64 b, u64 c) {
    u64 d; asm("fma.rn.f32x2 %0, %1, %2, %3;" : "=l"(d) : "l"(a), "l"(b), "l"(c)); return d;
}
__device__ __forceinline__ u64 add2(u64 a, u64 b) {
    u64 d; asm("add.rn.f32x2 %0, %1, %2;" : "=l"(d) : "l"(a), "l"(b)); return d;
}

__device__ __forceinline__ float sigf(float x) {
    return __fdividef(1.0f, 1.0f + __expf(-x));
}
// One LSTM cell update for one hidden unit. zi,zf,zg,zo are pre-activations.
__device__ __forceinline__ float cellf(float zi, float zf, float zg, float zo, float &c) {
    float i = sigf(zi);
    float f = sigf(zf);
    float g = fmaxf(zg, 0.0f);
    float o = sigf(zo);
    c = fmaf(f, c, i * g);
    return o * fmaxf(c, 0.0f);
}

// =====================================================================
// Kernel 1: xz[row][g] = sum_k x[row][k]*We[k][g] + be[g]
// row = b*T + t (524288 rows). Tile: 128 rows x 128 cols, K=64.
// x tile staged in smem (stride 65 to dodge bank conflicts), We via L1.
// Thread = 8 rows x 8 cols (4 f32x2 accumulators per row).
// =====================================================================
__global__ __launch_bounds__(256, 1) void k_xz(const float* __restrict__ x,
                                               const float* __restrict__ We,
                                               const float* __restrict__ be)
{
    __shared__ __align__(16) float xs[128 * 65];
    const int tid = threadIdx.x;
    const int mt = blockIdx.x;

    // Load x tile [128 rows x 64] as float4
    const float4* xsrc = (const float4*)(x + (size_t)mt * 128 * 64);
    for (int idx = tid; idx < 128 * 16; idx += 256) {
        int r = idx >> 4, kq = idx & 15;
        float4 v = __ldg(xsrc + idx);
        float* d = xs + r * 65 + kq * 4;
        d[0] = v.x; d[1] = v.y; d[2] = v.z; d[3] = v.w;
    }
    __syncthreads();

    const int tx = tid & 15, ty = tid >> 4;
    const int c0 = tx * 8;

    u64 acc[8][4];
#pragma unroll
    for (int i = 0; i < 8; i++)
#pragma unroll
        for (int j = 0; j < 4; j++) acc[i][j] = 0ULL;

    const float* xr = xs + ty * 8 * 65;

#pragma unroll 4
    for (int k = 0; k < 64; k++) {
        const float2* wp = (const float2*)(We + k * 128 + c0);
        u64 b0 = f2u(__ldg(wp + 0));
        u64 b1 = f2u(__ldg(wp + 1));
        u64 b2 = f2u(__ldg(wp + 2));
        u64 b3 = f2u(__ldg(wp + 3));
#pragma unroll
        for (int i = 0; i < 8; i++) {
            float a = xr[i * 65 + k];
            u64 a2 = pk2(a, a);
            acc[i][0] = fma2(a2, b0, acc[i][0]);
            acc[i][1] = fma2(a2, b1, acc[i][1]);
            acc[i][2] = fma2(a2, b2, acc[i][2]);
            acc[i][3] = fma2(a2, b3, acc[i][3]);
        }
    }

    u64 be2[4];
    const float2* bep = (const float2*)be + tx * 4;
#pragma unroll
    for (int j = 0; j < 4; j++) be2[j] = f2u(__ldg(bep + j));

    float2* outp = (float2*)g_xz;
#pragma unroll
    for (int i = 0; i < 8; i++) {
        size_t row = (size_t)mt * 128 + ty * 8 + i;
#pragma unroll
        for (int j = 0; j < 4; j++) {
            float lo, hi;
            upk2(add2(acc[i][j], be2[j]), lo, hi);
            outp[row * 64 + tx * 4 + j] = make_float2(lo, hi);
        }
    }
}

// =====================================================================
// Kernel 2: encoder recurrence. 128 CTAs x 32 batch rows, 256 threads.
// Thread = 2 rows x 2 hidden units x 4 gates (8 f32x2 accumulators).
// hx = tid&15 -> hidden pair k0=2*hx ; rw = tid>>4 -> row pair.
// h kept in smem [k][r] (stride 33); c in registers.
// xz streamed from gmem with one-step prefetch.
// =====================================================================
__global__ __launch_bounds__(256, 1) void k_enc(const float* __restrict__ Ue)
{
    __shared__ __align__(16) float Us[32 * 128];
    __shared__ __align__(16) float hs[32 * 33];
    const int tid = threadIdx.x;

    for (int i = tid; i < 32 * 128; i += 256) Us[i] = __ldg(Ue + i);
    for (int i = tid; i < 32 * 33; i += 256) hs[i] = 0.0f;

    const int hx = tid & 15, rw = tid >> 4;
    const int k0 = hx * 2;
    const int r0 = rw * 2, r1 = r0 + 1;
    const int b0r = blockIdx.x * 32 + r0;

    // float2 view of g_xz: element (b,t,g) -> float2 index (b*128+t)*64 + g/2
    const float2* xzr0 = (const float2*)g_xz + (size_t)b0r * 128 * 64;
    const float2* xzr1 = xzr0 + (size_t)128 * 64;

    float c00 = 0.f, c01 = 0.f, c10 = 0.f, c11 = 0.f;

    float2 cur[2][4];
#pragma unroll
    for (int g = 0; g < 4; g++) {
        cur[0][g] = __ldg(xzr0 + g * 16 + hx);
        cur[1][g] = __ldg(xzr1 + g * 16 + hx);
    }
    __syncthreads();

    for (int t = 0; t < 128; t++) {
        float2 nxt[2][4];
        if (t < 127) {
            const float2* p0 = xzr0 + (size_t)(t + 1) * 64;
            const float2* p1 = xzr1 + (size_t)(t + 1) * 64;
#pragma unroll
            for (int g = 0; g < 4; g++) {
                nxt[0][g] = __ldg(p0 + g * 16 + hx);
                nxt[1][g] = __ldg(p1 + g * 16 + hx);
            }
        }

        u64 acc[2][4];
#pragma unroll
        for (int g = 0; g < 4; g++) { acc[0][g] = f2u(cur[0][g]); acc[1][g] = f2u(cur[1][g]); }

#pragma unroll 8
        for (int kk = 0; kk < 32; kk++) {
            float hv0 = hs[kk * 33 + r0];
            float hv1 = hs[kk * 33 + r1];
            u64 h0 = pk2(hv0, hv0);
            u64 h1 = pk2(hv1, hv1);
            const float* urow = Us + kk * 128 + k0;
#pragma unroll
            for (int g = 0; g < 4; g++) {
                u64 w = f2u(*(const float2*)(urow + g * 32));
                acc[0][g] = fma2(h0, w, acc[0][g]);
                acc[1][g] = fma2(h1, w, acc[1][g]);
            }
        }
        __syncthreads();   // all reads of old h done

        float z[2][4][2];
#pragma unroll
        for (int r = 0; r < 2; r++)
#pragma unroll
            for (int g = 0; g < 4; g++) upk2(acc[r][g], z[r][g][0], z[r][g][1]);

        float h00 = cellf(z[0][0][0], z[0][1][0], z[0][2][0], z[0][3][0], c00);
        float h01 = cellf(z[0][0][1], z[0][1][1], z[0][2][1], z[0][3][1], c01);
        float h10 = cellf(z[1][0][0], z[1][1][0], z[1][2][0], z[1][3][0], c10);
        float h11 = cellf(z[1][0][1], z[1][1][1], z[1][2][1], z[1][3][1], c11);
        hs[k0 * 33 + r0] = h00;
        hs[(k0 + 1) * 33 + r0] = h01;
        hs[k0 * 33 + r1] = h10;
        hs[(k0 + 1) * 33 + r1] = h11;
        __syncthreads();   // new h visible

#pragma unroll
        for (int g = 0; g < 4; g++) { cur[0][g] = nxt[0][g]; cur[1][g] = nxt[1][g]; }
    }

    // write final hidden state hT
    for (int i = tid; i < 32 * 32; i += 256) {
        int r = i >> 5, k = i & 31;
        g_hT[(blockIdx.x * 32 + r) * 32 + k] = hs[k * 33 + r];
    }
}

// =====================================================================
// Kernel 3: decoder recurrence + fused Dense(64) output.
// zd = hT@Wd + bd computed once into smem (time-invariant input proj).
// Per step: z = zd + h@Ud ; gates ; then y_t = h_new@Wout + bout.
// =====================================================================
__global__ __launch_bounds__(256, 1) void k_dec(const float* __restrict__ Ud,
                                                const float* __restrict__ Wd,
                                                const float* __restrict__ bd,
                                                const float* __restrict__ Wout,
                                                const float* __restrict__ bout,
                                                float* __restrict__ y)
{
    __shared__ __align__(16) float Us[32 * 128];
    __shared__ __align__(16) float zds[32 * 128];
    __shared__ __align__(16) float Ws[32 * 66];
    __shared__ __align__(16) float hs[32 * 33];
    const int tid = threadIdx.x;

    for (int i = tid; i < 32 * 128; i += 256) Us[i] = __ldg(Ud + i);
    for (int i = tid; i < 32 * 64; i += 256) {
        int k = i >> 6, f = i & 63;
        Ws[k * 66 + f] = __ldg(Wout + i);
    }
    // stage hT into hs[k][r] temporarily (reused for zd computation)
    for (int i = tid; i < 32 * 32; i += 256) {
        int r = i >> 5, k = i & 31;
        hs[k * 33 + r] = __ldg(&g_hT[(blockIdx.x * 32 + r) * 32 + k]);
    }
    __syncthreads();

    const int hx = tid & 15, rw = tid >> 4;
    const int k0 = hx * 2;
    const int r0 = rw * 2, r1 = r0 + 1;

    // ---- zd = hT @ Wd + bd for our two rows ----
    {
        u64 a[2][4];
#pragma unroll
        for (int g = 0; g < 4; g++) {
            u64 b2 = f2u(__ldg((const float2*)bd + g * 16 + hx));
            a[0][g] = b2; a[1][g] = b2;
        }
#pragma unroll 8
        for (int kk = 0; kk < 32; kk++) {
            float hv0 = hs[kk * 33 + r0];
            float hv1 = hs[kk * 33 + r1];
            u64 h0 = pk2(hv0, hv0);
            u64 h1 = pk2(hv1, hv1);
            const float2* wrow = (const float2*)(Wd + kk * 128);
#pragma unroll
            for (int g = 0; g < 4; g++) {
                u64 w = f2u(__ldg(wrow + g * 16 + hx));
                a[0][g] = fma2(h0, w, a[0][g]);
                a[1][g] = fma2(h1, w, a[1][g]);
            }
        }
#pragma unroll
        for (int r = 0; r < 2; r++) {
            int rr = r ? r1 : r0;
#pragma unroll
            for (int g = 0; g < 4; g++) {
                float lo, hi; upk2(a[r][g], lo, hi);
                *(float2*)&zds[rr * 128 + g * 32 + k0] = make_float2(lo, hi);
            }
        }
    }
    __syncthreads();          // zd done; hs (hT) fully consumed
    for (int i = tid; i < 32 * 33; i += 256) hs[i] = 0.0f;   // decoder h0 = 0
    __syncthreads();

    float c00 = 0.f, c01 = 0.f, c10 = 0.f, c11 = 0.f;

    // output-GEMM thread mapping
    const int yrow = tid >> 3;
    const int yf0 = (tid & 7) * 8;
    u64 bo2[4];
#pragma unroll
    for (int j = 0; j < 4; j++) bo2[j] = f2u(__ldg((const float2*)bout + (tid & 7) * 4 + j));
    float2* ybase = (float2*)y + (size_t)(blockIdx.x * 32 + yrow) * 128 * 32;

    for (int t = 0; t < 128; t++) {
        u64 acc[2][4];
#pragma unroll
        for (int g = 0; g < 4; g++) {
            acc[0][g] = f2u(*(const float2*)&zds[r0 * 128 + g * 32 + k0]);
            acc[1][g] = f2u(*(const float2*)&zds[r1 * 128 + g * 32 + k0]);
        }

#pragma unroll 8
        for (int kk = 0; kk < 32; kk++) {
            float hv0 = hs[kk * 33 + r0];
            float hv1 = hs[kk * 33 + r1];
            u64 h0 = pk2(hv0, hv0);
            u64 h1 = pk2(hv1, hv1);
            const float* urow = Us + kk * 128 + k0;
#pragma unroll
            for (int g = 0; g < 4; g++) {
                u64 w = f2u(*(const float2*)(urow + g * 32));
                acc[0][g] = fma2(h0, w, acc[0][g]);
                acc[1][g] = fma2(h1, w, acc[1][g]);
            }
        }
        __syncthreads();   // old-h reads done (incl. prev step's y reads)

        float z[2][4][2];
#pragma unroll
        for (int r = 0; r < 2; r++)
#pragma unroll
            for (int g = 0; g < 4; g++) upk2(acc[r][g], z[r][g][0], z[r][g][1]);

        float h00 = cellf(z[0][0][0], z[0][1][0], z[0][2][0], z[0][3][0], c00);
        float h01 = cellf(z[0][0][1], z[0][1][1], z[0][2][1], z[0][3][1], c01);
        float h10 = cellf(z[1][0][0], z[1][1][0], z[1][2][0], z[1][3][0], c10);
        float h11 = cellf(z[1][0][1], z[1][1][1], z[1][2][1], z[1][3][1], c11);
        hs[k0 * 33 + r0] = h00;
        hs[(k0 + 1) * 33 + r0] = h01;
        hs[k0 * 33 + r1] = h10;
        hs[(k0 + 1) * 33 + r1] = h11;
        __syncthreads();   // new h visible

        // ---- y_t = h_new @ Wout + bout (this thread: 1 row x 8 cols) ----
        u64 ya[4];
#pragma unroll
        for (int j = 0; j < 4; j++) ya[j] = bo2[j];
#pragma unroll 8
        for (int kk = 0; kk < 32; kk++) {
            float hv = hs[kk * 33 + yrow];
            u64 h2 = pk2(hv, hv);
            const float* wr = Ws + kk * 66 + yf0;
#pragma unroll
            for (int j = 0; j < 4; j++)
                ya[j] = fma2(h2, f2u(*(const float2*)(wr + 2 * j)), ya[j]);
        }
#pragma unroll
        for (int j = 0; j < 4; j++) {
            float lo, hi; upk2(ya[j], lo, hi);
            ybase[(size_t)t * 32 + (tid & 7) * 4 + j] = make_float2(lo, hi);
        }
    }
}

// =====================================================================
extern "C" void kernel_launch(void* const* d_in, const int* in_sizes, int n_in,
                              void* d_out, int out_size)
{
    const float* x    = (const float*)d_in[0];
    const float* We   = (const float*)d_in[1];
    const float* Ue   = (const float*)d_in[2];
    const float* be   = (const float*)d_in[3];
    const float* Wd   = (const float*)d_in[4];
    const float* Ud   = (const float*)d_in[5];
    const float* bd   = (const float*)d_in[6];
    const float* Wout = (const float*)d_in[7];
    const float* bout = (const float*)d_in[8];
    float* y = (float*)d_out;

    k_xz<<<4096, 256>>>(x, We, be);
    k_enc<<<128, 256>>>(Ue);
    k_dec<<<128, 256>>>(Ud, Wd, bd, Wout, bout, y);
}

// round 2
// speedup vs baseline: 1.3870x; 1.3870x over previous
#include <cuda_runtime.h>

#define Bb 4096
#define Tt 128
#define Ff 64
#define Hh 32
#define Gg 128   // 4*H

__device__ float g_xz[(size_t)Bb * Tt * Gg];   // x@We + be, [b*T+t][128]
__device__ float g_hT[Bb * Hh];                // encoder final hidden

typedef unsigned long long u64;

// ---------- f32x2 packed helpers ----------
__device__ __forceinline__ u64 pk2(float lo, float hi) {
    u64 r; asm("mov.b64 %0, {%1, %2};" : "=l"(r) : "f"(lo), "f"(hi)); return r;
}
__device__ __forceinline__ void upk2(u64 v, float &lo, float &hi) {
    asm("mov.b64 {%0, %1}, %2;" : "=f"(lo), "=f"(hi) : "l"(v));
}
__device__ __forceinline__ u64 f2u(float2 v) { return pk2(v.x, v.y); }
__device__ __forceinline__ u64 fma2(u64 a, u64 b, u64 c) {
    u64 d; asm("fma.rn.f32x2 %0, %1, %2, %3;" : "=l"(d) : "l"(a), "l"(b), "l"(c)); return d;
}
__device__ __forceinline__ u64 add2(u64 a, u64 b) {
    u64 d; asm("add.rn.f32x2 %0, %1, %2;" : "=l"(d) : "l"(a), "l"(b)); return d;
}

__device__ __forceinline__ float sigf(float x) {
    return __fdividef(1.0f, 1.0f + __expf(-x));
}
__device__ __forceinline__ float cellf(float zi, float zf, float zg, float zo, float &c) {
    float i = sigf(zi);
    float f = sigf(zf);
    float g = fmaxf(zg, 0.0f);
    float o = sigf(zo);
    c = fmaf(f, c, i * g);
    return o * fmaxf(c, 0.0f);
}

// =====================================================================
// Kernel 1: xz = x @ We + be.  8192 CTAs x 64 rows. 256 thr, 2 CTAs/SM.
// We resident in smem, pair-swizzled layout ws2[k][j][tx] (float2) so the
// 16 lanes (tx) of a warp read banks 2*tx -> conflict-free LDS.64.
// Thread tile: 4 rows x 8 cols (16 u64 acc... 4x4 u64).
// =====================================================================
__global__ __launch_bounds__(256, 2) void k_xz(const float* __restrict__ x,
                                               const float* __restrict__ We,
                                               const float* __restrict__ be)
{
    __shared__ __align__(16) float2 ws2[64 * 64];       // 32 KB
    __shared__ __align__(16) float  xs[64 * 68];        // 17.4 KB (68: 16B-aligned rows)
    const int tid = threadIdx.x;

    // We [k][c] -> ws2[k*64 + j*16 + tx], where c-pair index c2 = tx*4 + j
    const float2* We2 = (const float2*)We;
    for (int i = tid; i < 64 * 64; i += 256) {
        int k = i >> 6, c2 = i & 63;
        int txd = c2 >> 2, j = c2 & 3;
        ws2[k * 64 + j * 16 + txd] = __ldg(We2 + i);
    }
    // x tile: 64 rows x 64
    const float4* xsrc = (const float4*)(x + (size_t)blockIdx.x * 64 * 64);
    for (int i = tid; i < 64 * 16; i += 256) {
        int r = i >> 4, kq = i & 15;
        *(float4*)(xs + r * 68 + kq * 4) = __ldg(xsrc + i);
    }
    __syncthreads();

    const int tx = tid & 15, ty = tid >> 4;

    u64 acc[4][4];
#pragma unroll
    for (int r = 0; r < 4; r++)
#pragma unroll
        for (int j = 0; j < 4; j++) acc[r][j] = 0ULL;

    const float* xr = xs + ty * 4 * 68;

#pragma unroll 4
    for (int kq = 0; kq < 16; kq++) {
        float4 xv[4];
#pragma unroll
        for (int r = 0; r < 4; r++) xv[r] = *(const float4*)(xr + r * 68 + kq * 4);
#pragma unroll
        for (int kk = 0; kk < 4; kk++) {
            int k = kq * 4 + kk;
            u64 b[4];
#pragma unroll
            for (int j = 0; j < 4; j++) b[j] = f2u(ws2[k * 64 + j * 16 + tx]);
#pragma unroll
            for (int r = 0; r < 4; r++) {
                float a = (&xv[r].x)[kk];
                u64 a2 = pk2(a, a);
#pragma unroll
                for (int j = 0; j < 4; j++) acc[r][j] = fma2(a2, b[j], acc[r][j]);
            }
        }
    }

    u64 be2[4];
    const float2* bep = (const float2*)be + tx * 4;
#pragma unroll
    for (int j = 0; j < 4; j++) be2[j] = f2u(__ldg(bep + j));

    float2* outp = (float2*)g_xz;
#pragma unroll
    for (int r = 0; r < 4; r++) {
        size_t row = (size_t)blockIdx.x * 64 + ty * 4 + r;
#pragma unroll
        for (int j = 0; j < 4; j++) {
            float lo, hi;
            upk2(add2(acc[r][j], be2[j]), lo, hi);
            outp[row * 64 + tx * 4 + j] = make_float2(lo, hi);
        }
    }
}

// =====================================================================
// Kernel 2: encoder recurrence. 128 CTAs x 32 rows, 256 thr.
// Thread = 2 rows x 2 hidden x 4 gates. Double-buffered h -> ONE sync/step.
// Us layout [kk][g*32+k] : float2 reads at k0=2*hx are conflict-free.
// =====================================================================
__global__ __launch_bounds__(256, 1) void k_enc(const float* __restrict__ Ue)
{
    __shared__ __align__(16) float Us[32 * 128];
    __shared__ __align__(16) float hbuf[2][32 * 33];
    const int tid = threadIdx.x;

    for (int i = tid; i < 32 * 128; i += 256) Us[i] = __ldg(Ue + i);
    for (int i = tid; i < 32 * 33; i += 256) hbuf[0][i] = 0.0f;

    const int hx = tid & 15, rw = tid >> 4;
    const int k0 = hx * 2;
    const int r0 = rw * 2, r1 = r0 + 1;
    const int b0r = blockIdx.x * 32 + r0;

    const float2* xzr0 = (const float2*)g_xz + (size_t)b0r * 128 * 64;
    const float2* xzr1 = xzr0 + (size_t)128 * 64;

    float c00 = 0.f, c01 = 0.f, c10 = 0.f, c11 = 0.f;

    float2 cur[2][4];
#pragma unroll
    for (int g = 0; g < 4; g++) {
        cur[0][g] = __ldg(xzr0 + g * 16 + hx);
        cur[1][g] = __ldg(xzr1 + g * 16 + hx);
    }
    __syncthreads();

    for (int t = 0; t < 128; t++) {
        const float* hp = hbuf[t & 1];
        float* hn = hbuf[(t & 1) ^ 1];

        float2 nxt[2][4];
        if (t < 127) {
            const float2* p0 = xzr0 + (size_t)(t + 1) * 64;
            const float2* p1 = xzr1 + (size_t)(t + 1) * 64;
#pragma unroll
            for (int g = 0; g < 4; g++) {
                nxt[0][g] = __ldg(p0 + g * 16 + hx);
                nxt[1][g] = __ldg(p1 + g * 16 + hx);
            }
        }

        u64 acc[2][4];
#pragma unroll
        for (int g = 0; g < 4; g++) { acc[0][g] = f2u(cur[0][g]); acc[1][g] = f2u(cur[1][g]); }

#pragma unroll 8
        for (int kk = 0; kk < 32; kk++) {
            float hv0 = hp[kk * 33 + r0];
            float hv1 = hp[kk * 33 + r1];
            u64 h0 = pk2(hv0, hv0);
            u64 h1 = pk2(hv1, hv1);
            const float* urow = Us + kk * 128 + k0;
#pragma unroll
            for (int g = 0; g < 4; g++) {
                u64 w = f2u(*(const float2*)(urow + g * 32));
                acc[0][g] = fma2(h0, w, acc[0][g]);
                acc[1][g] = fma2(h1, w, acc[1][g]);
            }
        }

        float z[2][4][2];
#pragma unroll
        for (int r = 0; r < 2; r++)
#pragma unroll
            for (int g = 0; g < 4; g++) upk2(acc[r][g], z[r][g][0], z[r][g][1]);

        hn[k0 * 33 + r0]       = cellf(z[0][0][0], z[0][1][0], z[0][2][0], z[0][3][0], c00);
        hn[(k0 + 1) * 33 + r0] = cellf(z[0][0][1], z[0][1][1], z[0][2][1], z[0][3][1], c01);
        hn[k0 * 33 + r1]       = cellf(z[1][0][0], z[1][1][0], z[1][2][0], z[1][3][0], c10);
        hn[(k0 + 1) * 33 + r1] = cellf(z[1][0][1], z[1][1][1], z[1][2][1], z[1][3][1], c11);
        __syncthreads();

#pragma unroll
        for (int g = 0; g < 4; g++) { cur[0][g] = nxt[0][g]; cur[1][g] = nxt[1][g]; }
    }

    // h_128 lives in hbuf[0] (last write at t=127 into buf (1^1)=0)
    for (int i = tid; i < 32 * 32; i += 256) {
        int r = i >> 5, k = i & 31;
        g_hT[(blockIdx.x * 32 + r) * 32 + k] = hbuf[0][k * 33 + r];
    }
}

// =====================================================================
// Kernel 3: decoder + fused Dense(64).
// Double-buffered h, one sync/step. y-GEMM for step t-1 is fused into
// step t's accumulation pass (both read the same buffer hp after the
// same barrier), so its FMAs/LDS interleave with the recurrence.
// =====================================================================
__global__ __launch_bounds__(256, 1) void k_dec(const float* __restrict__ Ud,
                                                const float* __restrict__ Wd,
                                                const float* __restrict__ bd,
                                                const float* __restrict__ Wout,
                                                const float* __restrict__ bout,
                                                float* __restrict__ y)
{
    __shared__ __align__(16) float  Us[32 * 128];
    __shared__ __align__(16) float  zds[32 * 128];
    __shared__ __align__(16) float2 Wsp[32 * 32];   // [k][j(0..3)][fg(0..7)]
    __shared__ __align__(16) float  hbuf[2][32 * 33];
    const int tid = threadIdx.x;

    for (int i = tid; i < 32 * 128; i += 256) Us[i] = __ldg(Ud + i);
    // Wout [k][f] -> Wsp[k*32 + j*8 + fg], pair index f2i = fg*4 + j
    const float2* Wout2 = (const float2*)Wout;
    for (int i = tid; i < 32 * 32; i += 256) {
        int k = i >> 5, f2i = i & 31;
        int fg = f2i >> 2, j = f2i & 3;
        Wsp[k * 32 + j * 8 + fg] = __ldg(Wout2 + i);
    }
    // stage hT into hbuf[1] as [k][r]
    for (int i = tid; i < 32 * 32; i += 256) {
        int r = i >> 5, k = i & 31;
        hbuf[1][k * 33 + r] = __ldg(&g_hT[(blockIdx.x * 32 + r) * 32 + k]);
    }
    __syncthreads();

    const int hx = tid & 15, rw = tid >> 4;
    const int k0 = hx * 2;
    const int r0 = rw * 2, r1 = r0 + 1;

    // ---- zd = hT @ Wd + bd ----
    {
        u64 a[2][4];
#pragma unroll
        for (int g = 0; g < 4; g++) {
            u64 b2 = f2u(__ldg((const float2*)bd + g * 16 + hx));
            a[0][g] = b2; a[1][g] = b2;
        }
#pragma unroll 8
        for (int kk = 0; kk < 32; kk++) {
            float hv0 = hbuf[1][kk * 33 + r0];
            float hv1 = hbuf[1][kk * 33 + r1];
            u64 h0 = pk2(hv0, hv0);
            u64 h1 = pk2(hv1, hv1);
            const float2* wrow = (const float2*)(Wd + kk * 128);
#pragma unroll
            for (int g = 0; g < 4; g++) {
                u64 w = f2u(__ldg(wrow + g * 16 + hx));
                a[0][g] = fma2(h0, w, a[0][g]);
                a[1][g] = fma2(h1, w, a[1][g]);
            }
        }
#pragma unroll
        for (int r = 0; r < 2; r++) {
            int rr = r ? r1 : r0;
#pragma unroll
            for (int g = 0; g < 4; g++) {
                float lo, hi; upk2(a[r][g], lo, hi);
                *(float2*)&zds[rr * 128 + g * 32 + k0] = make_float2(lo, hi);
            }
        }
    }
    __syncthreads();          // zd done; hbuf[1] consumed
    for (int i = tid; i < 32 * 33; i += 256) hbuf[0][i] = 0.0f;   // h0 = 0
    __syncthreads();

    float c00 = 0.f, c01 = 0.f, c10 = 0.f, c11 = 0.f;

    const int yrow = tid >> 3;
    const int fg = tid & 7;
    u64 bo2[4];
#pragma unroll
    for (int j = 0; j < 4; j++) bo2[j] = f2u(__ldg((const float2*)bout + fg * 4 + j));
    float2* ybase = (float2*)y + (size_t)(blockIdx.x * 32 + yrow) * 128 * 32;

    for (int t = 0; t < 128; t++) {
        const float* hp = hbuf[t & 1];       // h_t (h_0 = 0)
        float* hn = hbuf[(t & 1) ^ 1];

        u64 acc[2][4];
#pragma unroll
        for (int g = 0; g < 4; g++) {
            acc[0][g] = f2u(*(const float2*)&zds[r0 * 128 + g * 32 + k0]);
            acc[1][g] = f2u(*(const float2*)&zds[r1 * 128 + g * 32 + k0]);
        }
        u64 ya[4];
#pragma unroll
        for (int j = 0; j < 4; j++) ya[j] = bo2[j];

#pragma unroll 8
        for (int kk = 0; kk < 32; kk++) {
            float hv0 = hp[kk * 33 + r0];
            float hv1 = hp[kk * 33 + r1];
            u64 h0 = pk2(hv0, hv0);
            u64 h1 = pk2(hv1, hv1);
            const float* urow = Us + kk * 128 + k0;
#pragma unroll
            for (int g = 0; g < 4; g++) {
                u64 w = f2u(*(const float2*)(urow + g * 32));
                acc[0][g] = fma2(h0, w, acc[0][g]);
                acc[1][g] = fma2(h1, w, acc[1][g]);
            }
            // fused y-GEMM for step t-1 (uses h_t = hp)
            float hy = hp[kk * 33 + yrow];
            u64 h2 = pk2(hy, hy);
#pragma unroll
            for (int j = 0; j < 4; j++)
                ya[j] = fma2(h2, f2u(Wsp[kk * 32 + j * 8 + fg]), ya[j]);
        }

        if (t > 0) {
#pragma unroll
            for (int j = 0; j < 4; j++) {
                float lo, hi; upk2(ya[j], lo, hi);
                ybase[(size_t)(t - 1) * 32 + fg * 4 + j] = make_float2(lo, hi);
            }
        }

        float z[2][4][2];
#pragma unroll
        for (int r = 0; r < 2; r++)
#pragma unroll
            for (int g = 0; g < 4; g++) upk2(acc[r][g], z[r][g][0], z[r][g][1]);

        hn[k0 * 33 + r0]       = cellf(z[0][0][0], z[0][1][0], z[0][2][0], z[0][3][0], c00);
        hn[(k0 + 1) * 33 + r0] = cellf(z[0][0][1], z[0][1][1], z[0][2][1], z[0][3][1], c01);
        hn[k0 * 33 + r1]       = cellf(z[1][0][0], z[1][1][0], z[1][2][0], z[1][3][0], c10);
        hn[(k0 + 1) * 33 + r1] = cellf(z[1][0][1], z[1][1][1], z[1][2][1], z[1][3][1], c11);
        __syncthreads();
    }

    // epilogue: y[127] from h_128 = hbuf[0]
    {
        u64 ya[4];
#pragma unroll
        for (int j = 0; j < 4; j++) ya[j] = bo2[j];
#pragma unroll 8
        for (int kk = 0; kk < 32; kk++) {
            float hy = hbuf[0][kk * 33 + yrow];
            u64 h2 = pk2(hy, hy);
#pragma unroll
            for (int j = 0; j < 4; j++)
                ya[j] = fma2(h2, f2u(Wsp[kk * 32 + j * 8 + fg]), ya[j]);
        }
#pragma unroll
        for (int j = 0; j < 4; j++) {
            float lo, hi; upk2(ya[j], lo, hi);
            ybase[(size_t)127 * 32 + fg * 4 + j] = make_float2(lo, hi);
        }
    }
}

// =====================================================================
extern "C" void kernel_launch(void* const* d_in, const int* in_sizes, int n_in,
                              void* d_out, int out_size)
{
    const float* x    = (const float*)d_in[0];
    const float* We   = (const float*)d_in[1];
    const float* Ue   = (const float*)d_in[2];
    const float* be   = (const float*)d_in[3];
    const float* Wd   = (const float*)d_in[4];
    const float* Ud   = (const float*)d_in[5];
    const float* bd   = (const float*)d_in[6];
    const float* Wout = (const float*)d_in[7];
    const float* bout = (const float*)d_in[8];
    float* y = (float*)d_out;

    k_xz<<<8192, 256>>>(x, We, be);
    k_enc<<<128, 256>>>(Ue);
    k_dec<<<128, 256>>>(Ud, Wd, bd, Wout, bout, y);
}

// round 3
// speedup vs baseline: 1.7154x; 1.2368x over previous
#include <cuda_runtime.h>

#define Bb 4096
#define Tt 128
#define Ff 64
#define Hh 32
#define Gg 128   // 4*H

__device__ float g_xz[(size_t)Bb * Tt * Gg];   // x@We + be, [b*T+t][128]
__device__ float g_hT[Bb * Hh];                // encoder final hidden

typedef unsigned long long u64;

// ---------- f32x2 packed helpers ----------
__device__ __forceinline__ u64 pk2(float lo, float hi) {
    u64 r; asm("mov.b64 %0, {%1, %2};" : "=l"(r) : "f"(lo), "f"(hi)); return r;
}
__device__ __forceinline__ void upk2(u64 v, float &lo, float &hi) {
    asm("mov.b64 {%0, %1}, %2;" : "=f"(lo), "=f"(hi) : "l"(v));
}
__device__ __forceinline__ u64 f2u(float2 v) { return pk2(v.x, v.y); }
__device__ __forceinline__ u64 fma2(u64 a, u64 b, u64 c) {
    u64 d; asm("fma.rn.f32x2 %0, %1, %2, %3;" : "=l"(d) : "l"(a), "l"(b), "l"(c)); return d;
}
__device__ __forceinline__ u64 add2(u64 a, u64 b) {
    u64 d; asm("add.rn.f32x2 %0, %1, %2;" : "=l"(d) : "l"(a), "l"(b)); return d;
}

__device__ __forceinline__ float sigf(float x) {
    return __fdividef(1.0f, 1.0f + __expf(-x));
}
__device__ __forceinline__ float cellf(float zi, float zf, float zg, float zo, float &c) {
    float i = sigf(zi);
    float f = sigf(zf);
    float g = fmaxf(zg, 0.0f);
    float o = sigf(zo);
    c = fmaf(f, c, i * g);
    return o * fmaxf(c, 0.0f);
}

// =====================================================================
// Kernel 1: xz = x @ We + be.  8192 CTAs x 64 rows, 128 threads, 3 CTA/SM.
// Thread tile: 8 rows x 8 cols. Column-pair owned by (tx,j) is j*16+tx,
// so ws2 is an IDENTITY copy of We (float2): conflict-free stores+loads,
// coalesced output stores.
// =====================================================================
__global__ __launch_bounds__(128, 3) void k_xz(const float* __restrict__ x,
                                               const float* __restrict__ We,
                                               const float* __restrict__ be)
{
    __shared__ __align__(16) float2 ws2[64 * 64];   // 32 KB, verbatim We
    __shared__ __align__(16) float  xs[64 * 64];    // 16 KB
    const int tid = threadIdx.x;

    const float2* We2 = (const float2*)We;
    for (int i = tid; i < 64 * 64; i += 128) ws2[i] = __ldg(We2 + i);
    const float4* xsrc = (const float4*)(x + (size_t)blockIdx.x * 64 * 64);
    for (int i = tid; i < 64 * 16; i += 128) {
        *(float4*)(xs + i * 4) = __ldg(xsrc + i);
    }
    __syncthreads();

    const int tx = tid & 15, ty = tid >> 4;

    u64 acc[8][4];
#pragma unroll
    for (int r = 0; r < 8; r++)
#pragma unroll
        for (int j = 0; j < 4; j++) acc[r][j] = 0ULL;

    const float* xr = xs + ty * 8 * 64;

#pragma unroll 2
    for (int kq = 0; kq < 16; kq++) {
        float4 xv[8];
#pragma unroll
        for (int r = 0; r < 8; r++) xv[r] = *(const float4*)(xr + r * 64 + kq * 4);
#pragma unroll
        for (int kk = 0; kk < 4; kk++) {
            int k = kq * 4 + kk;
            u64 b[4];
#pragma unroll
            for (int j = 0; j < 4; j++) b[j] = f2u(ws2[k * 64 + j * 16 + tx]);
#pragma unroll
            for (int r = 0; r < 8; r++) {
                float a = (&xv[r].x)[kk];
                u64 a2 = pk2(a, a);
#pragma unroll
                for (int j = 0; j < 4; j++) acc[r][j] = fma2(a2, b[j], acc[r][j]);
            }
        }
    }

    u64 be2[4];
#pragma unroll
    for (int j = 0; j < 4; j++) be2[j] = f2u(__ldg((const float2*)be + j * 16 + tx));

    float2* outp = (float2*)g_xz;
#pragma unroll
    for (int r = 0; r < 8; r++) {
        size_t row = (size_t)blockIdx.x * 64 + ty * 8 + r;
#pragma unroll
        for (int j = 0; j < 4; j++) {
            float lo, hi;
            upk2(add2(acc[r][j], be2[j]), lo, hi);
            outp[row * 64 + j * 16 + tx] = make_float2(lo, hi);
        }
    }
}

// =====================================================================
// Kernel 2: encoder recurrence. 256 CTAs x 16 rows, 128 threads, 4 CTA/SM.
// Thread = 2 rows x 2 hidden x 4 gates. Double-buffered h, ONE sync/step.
// =====================================================================
__global__ __launch_bounds__(128, 4) void k_enc(const float* __restrict__ Ue)
{
    __shared__ __align__(16) float Us[32 * 128];
    __shared__ __align__(16) float hbuf[2][32 * 17];
    const int tid = threadIdx.x;

    for (int i = tid; i < 32 * 128; i += 128) Us[i] = __ldg(Ue + i);
    for (int i = tid; i < 32 * 17; i += 128) hbuf[0][i] = 0.0f;

    const int hx = tid & 15, rw = tid >> 4;     // hx 0..15, rw 0..7
    const int k0 = hx * 2;
    const int r0 = rw * 2, r1 = r0 + 1;
    const int b0r = blockIdx.x * 16 + r0;

    const float2* xzr0 = (const float2*)g_xz + (size_t)b0r * 128 * 64;
    const float2* xzr1 = xzr0 + (size_t)128 * 64;

    float c00 = 0.f, c01 = 0.f, c10 = 0.f, c11 = 0.f;

    float2 cur[2][4];
#pragma unroll
    for (int g = 0; g < 4; g++) {
        cur[0][g] = __ldg(xzr0 + g * 16 + hx);
        cur[1][g] = __ldg(xzr1 + g * 16 + hx);
    }
    __syncthreads();

    for (int t = 0; t < 128; t++) {
        const float* hp = hbuf[t & 1];
        float* hn = hbuf[(t & 1) ^ 1];

        float2 nxt[2][4];
        if (t < 127) {
            const float2* p0 = xzr0 + (size_t)(t + 1) * 64;
            const float2* p1 = xzr1 + (size_t)(t + 1) * 64;
#pragma unroll
            for (int g = 0; g < 4; g++) {
                nxt[0][g] = __ldg(p0 + g * 16 + hx);
                nxt[1][g] = __ldg(p1 + g * 16 + hx);
            }
        }

        u64 acc[2][4];
#pragma unroll
        for (int g = 0; g < 4; g++) { acc[0][g] = f2u(cur[0][g]); acc[1][g] = f2u(cur[1][g]); }

#pragma unroll 8
        for (int kk = 0; kk < 32; kk++) {
            float hv0 = hp[kk * 17 + r0];
            float hv1 = hp[kk * 17 + r1];
            u64 h0 = pk2(hv0, hv0);
            u64 h1 = pk2(hv1, hv1);
            const float* urow = Us + kk * 128 + k0;
#pragma unroll
            for (int g = 0; g < 4; g++) {
                u64 w = f2u(*(const float2*)(urow + g * 32));
                acc[0][g] = fma2(h0, w, acc[0][g]);
                acc[1][g] = fma2(h1, w, acc[1][g]);
            }
        }

        float z[2][4][2];
#pragma unroll
        for (int r = 0; r < 2; r++)
#pragma unroll
            for (int g = 0; g < 4; g++) upk2(acc[r][g], z[r][g][0], z[r][g][1]);

        hn[k0 * 17 + r0]       = cellf(z[0][0][0], z[0][1][0], z[0][2][0], z[0][3][0], c00);
        hn[(k0 + 1) * 17 + r0] = cellf(z[0][0][1], z[0][1][1], z[0][2][1], z[0][3][1], c01);
        hn[k0 * 17 + r1]       = cellf(z[1][0][0], z[1][1][0], z[1][2][0], z[1][3][0], c10);
        hn[(k0 + 1) * 17 + r1] = cellf(z[1][0][1], z[1][1][1], z[1][2][1], z[1][3][1], c11);
        __syncthreads();

#pragma unroll
        for (int g = 0; g < 4; g++) { cur[0][g] = nxt[0][g]; cur[1][g] = nxt[1][g]; }
    }

    // h_128 in hbuf[0]
    for (int i = tid; i < 16 * 32; i += 128) {
        int r = i >> 5, k = i & 31;
        g_hT[(blockIdx.x * 16 + r) * 32 + k] = hbuf[0][k * 17 + r];
    }
}

// =====================================================================
// Kernel 3: decoder + fused Dense(64). 256 CTAs x 16 rows, 128 thr, 3 CTA/SM.
// y-GEMM for step t-1 fused into step t's accumulation pass.
// Wsp identity copy of Wout (f-pair owned by (fg,j) = j*8+fg).
// =====================================================================
__global__ __launch_bounds__(128, 3) void k_dec(const float* __restrict__ Ud,
                                                const float* __restrict__ Wd,
                                                const float* __restrict__ bd,
                                                const float* __restrict__ Wout,
                                                const float* __restrict__ bout,
                                                float* __restrict__ y)
{
    __shared__ __align__(16) float  Us[32 * 128];
    __shared__ __align__(16) float  zds[16 * 128];
    __shared__ __align__(16) float2 Wsp[32 * 32];   // verbatim Wout (float2)
    __shared__ __align__(16) float  hbuf[2][32 * 17];
    const int tid = threadIdx.x;

    for (int i = tid; i < 32 * 128; i += 128) Us[i] = __ldg(Ud + i);
    const float2* Wout2 = (const float2*)Wout;
    for (int i = tid; i < 32 * 32; i += 128) Wsp[i] = __ldg(Wout2 + i);
    // stage hT into hbuf[1] as [k][r]
    for (int i = tid; i < 16 * 32; i += 128) {
        int r = i >> 5, k = i & 31;
        hbuf[1][k * 17 + r] = __ldg(&g_hT[(blockIdx.x * 16 + r) * 32 + k]);
    }
    __syncthreads();

    const int hx = tid & 15, rw = tid >> 4;
    const int k0 = hx * 2;
    const int r0 = rw * 2, r1 = r0 + 1;

    // ---- zd = hT @ Wd + bd ----
    {
        u64 a[2][4];
#pragma unroll
        for (int g = 0; g < 4; g++) {
            u64 b2 = f2u(__ldg((const float2*)bd + g * 16 + hx));
            a[0][g] = b2; a[1][g] = b2;
        }
#pragma unroll 8
        for (int kk = 0; kk < 32; kk++) {
            float hv0 = hbuf[1][kk * 17 + r0];
            float hv1 = hbuf[1][kk * 17 + r1];
            u64 h0 = pk2(hv0, hv0);
            u64 h1 = pk2(hv1, hv1);
            const float2* wrow = (const float2*)(Wd + kk * 128);
#pragma unroll
            for (int g = 0; g < 4; g++) {
                u64 w = f2u(__ldg(wrow + g * 16 + hx));
                a[0][g] = fma2(h0, w, a[0][g]);
                a[1][g] = fma2(h1, w, a[1][g]);
            }
        }
#pragma unroll
        for (int r = 0; r < 2; r++) {
            int rr = r ? r1 : r0;
#pragma unroll
            for (int g = 0; g < 4; g++) {
                float lo, hi; upk2(a[r][g], lo, hi);
                *(float2*)&zds[rr * 128 + g * 32 + k0] = make_float2(lo, hi);
            }
        }
    }
    __syncthreads();          // zd done; hbuf[1] consumed
    for (int i = tid; i < 32 * 17; i += 128) hbuf[0][i] = 0.0f;   // h0 = 0
    __syncthreads();

    float c00 = 0.f, c01 = 0.f, c10 = 0.f, c11 = 0.f;

    const int yrow = tid >> 3;       // 0..15
    const int fg = tid & 7;          // 0..7 ; f-pair = j*8+fg
    u64 bo2[4];
#pragma unroll
    for (int j = 0; j < 4; j++) bo2[j] = f2u(__ldg((const float2*)bout + j * 8 + fg));
    float2* ybase = (float2*)y + (size_t)(blockIdx.x * 16 + yrow) * 128 * 32;

    for (int t = 0; t < 128; t++) {
        const float* hp = hbuf[t & 1];       // h_t (h_0 = 0)
        float* hn = hbuf[(t & 1) ^ 1];

        u64 acc[2][4];
#pragma unroll
        for (int g = 0; g < 4; g++) {
            acc[0][g] = f2u(*(const float2*)&zds[r0 * 128 + g * 32 + k0]);
            acc[1][g] = f2u(*(const float2*)&zds[r1 * 128 + g * 32 + k0]);
        }
        u64 ya[4];
#pragma unroll
        for (int j = 0; j < 4; j++) ya[j] = bo2[j];

#pragma unroll 8
        for (int kk = 0; kk < 32; kk++) {
            float hv0 = hp[kk * 17 + r0];
            float hv1 = hp[kk * 17 + r1];
            u64 h0 = pk2(hv0, hv0);
            u64 h1 = pk2(hv1, hv1);
            const float* urow = Us + kk * 128 + k0;
#pragma unroll
            for (int g = 0; g < 4; g++) {
                u64 w = f2u(*(const float2*)(urow + g * 32));
                acc[0][g] = fma2(h0, w, acc[0][g]);
                acc[1][g] = fma2(h1, w, acc[1][g]);
            }
            // fused y-GEMM for step t-1 (uses h_t = hp)
            float hy = hp[kk * 17 + yrow];
            u64 h2 = pk2(hy, hy);
#pragma unroll
            for (int j = 0; j < 4; j++)
                ya[j] = fma2(h2, f2u(Wsp[kk * 32 + j * 8 + fg]), ya[j]);
        }

        if (t > 0) {
#pragma unroll
            for (int j = 0; j < 4; j++) {
                float lo, hi; upk2(ya[j], lo, hi);
                ybase[(size_t)(t - 1) * 32 + j * 8 + fg] = make_float2(lo, hi);
            }
        }

        float z[2][4][2];
#pragma unroll
        for (int r = 0; r < 2; r++)
#pragma unroll
            for (int g = 0; g < 4; g++) upk2(acc[r][g], z[r][g][0], z[r][g][1]);

        hn[k0 * 17 + r0]       = cellf(z[0][0][0], z[0][1][0], z[0][2][0], z[0][3][0], c00);
        hn[(k0 + 1) * 17 + r0] = cellf(z[0][0][1], z[0][1][1], z[0][2][1], z[0][3][1], c01);
        hn[k0 * 17 + r1]       = cellf(z[1][0][0], z[1][1][0], z[1][2][0], z[1][3][0], c10);
        hn[(k0 + 1) * 17 + r1] = cellf(z[1][0][1], z[1][1][1], z[1][2][1], z[1][3][1], c11);
        __syncthreads();
    }

    // epilogue: y[127] from h_128 = hbuf[0]
    {
        u64 ya[4];
#pragma unroll
        for (int j = 0; j < 4; j++) ya[j] = bo2[j];
#pragma unroll 8
        for (int kk = 0; kk < 32; kk++) {
            float hy = hbuf[0][kk * 17 + yrow];
            u64 h2 = pk2(hy, hy);
#pragma unroll
            for (int j = 0; j < 4; j++)
                ya[j] = fma2(h2, f2u(Wsp[kk * 32 + j * 8 + fg]), ya[j]);
        }
#pragma unroll
        for (int j = 0; j < 4; j++) {
            float lo, hi; upk2(ya[j], lo, hi);
            ybase[(size_t)127 * 32 + j * 8 + fg] = make_float2(lo, hi);
        }
    }
}

// =====================================================================
extern "C" void kernel_launch(void* const* d_in, const int* in_sizes, int n_in,
                              void* d_out, int out_size)
{
    const float* x    = (const float*)d_in[0];
    const float* We   = (const float*)d_in[1];
    const float* Ue   = (const float*)d_in[2];
    const float* be   = (const float*)d_in[3];
    const float* Wd   = (const float*)d_in[4];
    const float* Ud   = (const float*)d_in[5];
    const float* bd   = (const float*)d_in[6];
    const float* Wout = (const float*)d_in[7];
    const float* bout = (const float*)d_in[8];
    float* y = (float*)d_out;

    k_xz<<<8192, 128>>>(x, We, be);
    k_enc<<<256, 128>>>(Ue);
    k_dec<<<256, 128>>>(Ud, Wd, bd, Wout, bout, y);
}

// round 4
// speedup vs baseline: 2.2416x; 1.3068x over previous
#include <cuda_runtime.h>

#define Bb 4096
#define Tt 128
#define Ff 64
#define Hh 32
#define Gg 128   // 4*H

__device__ float g_xz[(size_t)Bb * Tt * Gg];   // x@We + be, [b*T+t][128]
__device__ float g_hT[Bb * Hh];                // encoder final hidden

typedef unsigned long long u64;

// ---------- f32x2 packed helpers ----------
__device__ __forceinline__ u64 pk2(float lo, float hi) {
    u64 r; asm("mov.b64 %0, {%1, %2};" : "=l"(r) : "f"(lo), "f"(hi)); return r;
}
__device__ __forceinline__ void upk2(u64 v, float &lo, float &hi) {
    asm("mov.b64 {%0, %1}, %2;" : "=f"(lo), "=f"(hi) : "l"(v));
}
__device__ __forceinline__ u64 f2u(float2 v) { return pk2(v.x, v.y); }
__device__ __forceinline__ u64 fma2(u64 a, u64 b, u64 c) {
    u64 d; asm("fma.rn.f32x2 %0, %1, %2, %3;" : "=l"(d) : "l"(a), "l"(b), "l"(c)); return d;
}
__device__ __forceinline__ u64 add2(u64 a, u64 b) {
    u64 d; asm("add.rn.f32x2 %0, %1, %2;" : "=l"(d) : "l"(a), "l"(b)); return d;
}

__device__ __forceinline__ float sigf(float x) {
    return __fdividef(1.0f, 1.0f + __expf(-x));
}
__device__ __forceinline__ float cellf(float zi, float zf, float zg, float zo, float &c) {
    float i = sigf(zi);
    float f = sigf(zf);
    float g = fmaxf(zg, 0.0f);
    float o = sigf(zo);
    c = fmaf(f, c, i * g);
    return o * fmaxf(c, 0.0f);
}

// =====================================================================
// Kernel 1: xz = x @ We + be.  (unchanged from round 3: 185us, fma 59%)
// =====================================================================
__global__ __launch_bounds__(128, 3) void k_xz(const float* __restrict__ x,
                                               const float* __restrict__ We,
                                               const float* __restrict__ be)
{
    __shared__ __align__(16) float2 ws2[64 * 64];   // 32 KB, verbatim We
    __shared__ __align__(16) float  xs[64 * 64];    // 16 KB
    const int tid = threadIdx.x;

    const float2* We2 = (const float2*)We;
    for (int i = tid; i < 64 * 64; i += 128) ws2[i] = __ldg(We2 + i);
    const float4* xsrc = (const float4*)(x + (size_t)blockIdx.x * 64 * 64);
    for (int i = tid; i < 64 * 16; i += 128) {
        *(float4*)(xs + i * 4) = __ldg(xsrc + i);
    }
    __syncthreads();

    const int tx = tid & 15, ty = tid >> 4;

    u64 acc[8][4];
#pragma unroll
    for (int r = 0; r < 8; r++)
#pragma unroll
        for (int j = 0; j < 4; j++) acc[r][j] = 0ULL;

    const float* xr = xs + ty * 8 * 64;

#pragma unroll 2
    for (int kq = 0; kq < 16; kq++) {
        float4 xv[8];
#pragma unroll
        for (int r = 0; r < 8; r++) xv[r] = *(const float4*)(xr + r * 64 + kq * 4);
#pragma unroll
        for (int kk = 0; kk < 4; kk++) {
            int k = kq * 4 + kk;
            u64 b[4];
#pragma unroll
            for (int j = 0; j < 4; j++) b[j] = f2u(ws2[k * 64 + j * 16 + tx]);
#pragma unroll
            for (int r = 0; r < 8; r++) {
                float a = (&xv[r].x)[kk];
                u64 a2 = pk2(a, a);
#pragma unroll
                for (int j = 0; j < 4; j++) acc[r][j] = fma2(a2, b[j], acc[r][j]);
            }
        }
    }

    u64 be2[4];
#pragma unroll
    for (int j = 0; j < 4; j++) be2[j] = f2u(__ldg((const float2*)be + j * 16 + tx));

    float2* outp = (float2*)g_xz;
#pragma unroll
    for (int r = 0; r < 8; r++) {
        size_t row = (size_t)blockIdx.x * 64 + ty * 8 + r;
#pragma unroll
        for (int j = 0; j < 4; j++) {
            float lo, hi;
            upk2(add2(acc[r][j], be2[j]), lo, hi);
            outp[row * 64 + j * 16 + tx] = make_float2(lo, hi);
        }
    }
}

// =====================================================================
// Kernel 2: encoder recurrence — register-resident U + shuffle h.
// Warp = 2 batch rows. Lane l = hidden unit l. No smem, no barriers.
// U packed as gate-pairs: wif[kk]=(U[kk][l],U[kk][32+l]) (i,f),
//                         wgo[kk]=(U[kk][64+l],U[kk][96+l]) (g,o).
// 512 CTAs x 128 threads (8 rows/CTA).
// =====================================================================
__global__ __launch_bounds__(128) void k_enc(const float* __restrict__ Ue)
{
    const int lane = threadIdx.x & 31;
    const int gwarp = blockIdx.x * 4 + (threadIdx.x >> 5);
    const int row0 = gwarp * 2;

    u64 wif[32], wgo[32];
#pragma unroll
    for (int kk = 0; kk < 32; kk++) {
        const float* u = Ue + kk * 128;
        wif[kk] = pk2(__ldg(u + lane),      __ldg(u + 32 + lane));
        wgo[kk] = pk2(__ldg(u + 64 + lane), __ldg(u + 96 + lane));
    }

    const float* xzr0 = g_xz + (size_t)row0 * 128 * 128;   // [t][128]
    const float* xzr1 = xzr0 + 128 * 128;

    float h0 = 0.f, h1 = 0.f, cc0 = 0.f, cc1 = 0.f;

    // prefetch t = 0
    u64 nif0 = pk2(__ldg(xzr0 + lane),      __ldg(xzr0 + 32 + lane));
    u64 ngo0 = pk2(__ldg(xzr0 + 64 + lane), __ldg(xzr0 + 96 + lane));
    u64 nif1 = pk2(__ldg(xzr1 + lane),      __ldg(xzr1 + 32 + lane));
    u64 ngo1 = pk2(__ldg(xzr1 + 64 + lane), __ldg(xzr1 + 96 + lane));

    for (int t = 0; t < 128; t++) {
        u64 aif0 = nif0, ago0 = ngo0, aif1 = nif1, ago1 = ngo1;

        if (t < 127) {   // prefetch next step's xz (hides DRAM latency)
            const float* p0 = xzr0 + (size_t)(t + 1) * 128;
            const float* p1 = xzr1 + (size_t)(t + 1) * 128;
            nif0 = pk2(__ldg(p0 + lane),      __ldg(p0 + 32 + lane));
            ngo0 = pk2(__ldg(p0 + 64 + lane), __ldg(p0 + 96 + lane));
            nif1 = pk2(__ldg(p1 + lane),      __ldg(p1 + 32 + lane));
            ngo1 = pk2(__ldg(p1 + 64 + lane), __ldg(p1 + 96 + lane));
        }

#pragma unroll
        for (int kk = 0; kk < 32; kk++) {
            float hv0 = __shfl_sync(0xffffffffu, h0, kk);
            float hv1 = __shfl_sync(0xffffffffu, h1, kk);
            u64 hp0 = pk2(hv0, hv0);
            u64 hp1 = pk2(hv1, hv1);
            aif0 = fma2(hp0, wif[kk], aif0);
            ago0 = fma2(hp0, wgo[kk], ago0);
            aif1 = fma2(hp1, wif[kk], aif1);
            ago1 = fma2(hp1, wgo[kk], ago1);
        }

        float zi, zf, zg, zo;
        upk2(aif0, zi, zf); upk2(ago0, zg, zo);
        h0 = cellf(zi, zf, zg, zo, cc0);
        upk2(aif1, zi, zf); upk2(ago1, zg, zo);
        h1 = cellf(zi, zf, zg, zo, cc1);
    }

    g_hT[(size_t)row0 * 32 + lane] = h0;
    g_hT[(size_t)(row0 + 1) * 32 + lane] = h1;
}

// =====================================================================
// Kernel 3: decoder recurrence + fused Dense(64).
// Same structure. zd = hT@Wd + bd computed ONCE into registers.
// Wout staged once into smem as packed u64 (one LDS.64 per kk).
// y for step t-1 computed in step t's loop (uses pre-update h = hs[t-1]).
// =====================================================================
__global__ __launch_bounds__(128) void k_dec(const float* __restrict__ Ud,
                                             const float* __restrict__ Wd,
                                             const float* __restrict__ bd,
                                             const float* __restrict__ Wout,
                                             const float* __restrict__ bout,
                                             float* __restrict__ y)
{
    __shared__ __align__(16) u64 Wos[32 * 32];   // 8KB: (Wout[kk][l], Wout[kk][32+l])
    const int tid = threadIdx.x;
    const int lane = tid & 31;
    const int gwarp = blockIdx.x * 4 + (tid >> 5);
    const int row0 = gwarp * 2;

    for (int i = tid; i < 32 * 32; i += 128) {
        int kk = i >> 5, l = i & 31;
        Wos[i] = pk2(__ldg(Wout + kk * 64 + l), __ldg(Wout + kk * 64 + 32 + l));
    }

    u64 wif[32], wgo[32];
#pragma unroll
    for (int kk = 0; kk < 32; kk++) {
        const float* u = Ud + kk * 128;
        wif[kk] = pk2(__ldg(u + lane),      __ldg(u + 32 + lane));
        wgo[kk] = pk2(__ldg(u + 64 + lane), __ldg(u + 96 + lane));
    }
    __syncthreads();

    // ---- zd = hT @ Wd + bd (once, into registers) ----
    float ht0 = __ldg(&g_hT[(size_t)row0 * 32 + lane]);
    float ht1 = __ldg(&g_hT[(size_t)(row0 + 1) * 32 + lane]);
    u64 zif0 = pk2(__ldg(bd + lane),      __ldg(bd + 32 + lane));
    u64 zgo0 = pk2(__ldg(bd + 64 + lane), __ldg(bd + 96 + lane));
    u64 zif1 = zif0, zgo1 = zgo0;
#pragma unroll
    for (int kk = 0; kk < 32; kk++) {
        float hv0 = __shfl_sync(0xffffffffu, ht0, kk);
        float hv1 = __shfl_sync(0xffffffffu, ht1, kk);
        const float* w = Wd + kk * 128;
        u64 vif = pk2(__ldg(w + lane),      __ldg(w + 32 + lane));
        u64 vgo = pk2(__ldg(w + 64 + lane), __ldg(w + 96 + lane));
        u64 hp0 = pk2(hv0, hv0);
        u64 hp1 = pk2(hv1, hv1);
        zif0 = fma2(hp0, vif, zif0);
        zgo0 = fma2(hp0, vgo, zgo0);
        zif1 = fma2(hp1, vif, zif1);
        zgo1 = fma2(hp1, vgo, zgo1);
    }

    float h0 = 0.f, h1 = 0.f, cc0 = 0.f, cc1 = 0.f;
    u64 bo = pk2(__ldg(bout + lane), __ldg(bout + 32 + lane));
    float* y0 = y + (size_t)row0 * 128 * 64;
    float* y1 = y0 + 128 * 64;

    for (int t = 0; t < 128; t++) {
        u64 aif0 = zif0, ago0 = zgo0, aif1 = zif1, ago1 = zgo1;
        u64 ya0 = bo, ya1 = bo;

#pragma unroll
        for (int kk = 0; kk < 32; kk++) {
            float hv0 = __shfl_sync(0xffffffffu, h0, kk);
            float hv1 = __shfl_sync(0xffffffffu, h1, kk);
            u64 hp0 = pk2(hv0, hv0);
            u64 hp1 = pk2(hv1, hv1);
            aif0 = fma2(hp0, wif[kk], aif0);
            ago0 = fma2(hp0, wgo[kk], ago0);
            aif1 = fma2(hp1, wif[kk], aif1);
            ago1 = fma2(hp1, wgo[kk], ago1);
            u64 wo = Wos[kk * 32 + lane];
            ya0 = fma2(hp0, wo, ya0);
            ya1 = fma2(hp1, wo, ya1);
        }

        if (t > 0) {   // ya used h_t = hs[t-1] -> this is y[t-1]
            float a, b;
            upk2(ya0, a, b);
            y0[(size_t)(t - 1) * 64 + lane] = a;
            y0[(size_t)(t - 1) * 64 + 32 + lane] = b;
            upk2(ya1, a, b);
            y1[(size_t)(t - 1) * 64 + lane] = a;
            y1[(size_t)(t - 1) * 64 + 32 + lane] = b;
        }

        float zi, zf, zg, zo;
        upk2(aif0, zi, zf); upk2(ago0, zg, zo);
        h0 = cellf(zi, zf, zg, zo, cc0);
        upk2(aif1, zi, zf); upk2(ago1, zg, zo);
        h1 = cellf(zi, zf, zg, zo, cc1);
    }

    // epilogue: y[127] from final h (= hs[127])
    {
        u64 ya0 = bo, ya1 = bo;
#pragma unroll
        for (int kk = 0; kk < 32; kk++) {
            float hv0 = __shfl_sync(0xffffffffu, h0, kk);
            float hv1 = __shfl_sync(0xffffffffu, h1, kk);
            u64 wo = Wos[kk * 32 + lane];
            ya0 = fma2(pk2(hv0, hv0), wo, ya0);
            ya1 = fma2(pk2(hv1, hv1), wo, ya1);
        }
        float a, b;
        upk2(ya0, a, b);
        y0[(size_t)127 * 64 + lane] = a;
        y0[(size_t)127 * 64 + 32 + lane] = b;
        upk2(ya1, a, b);
        y1[(size_t)127 * 64 + lane] = a;
        y1[(size_t)127 * 64 + 32 + lane] = b;
    }
}

// =====================================================================
extern "C" void kernel_launch(void* const* d_in, const int* in_sizes, int n_in,
                              void* d_out, int out_size)
{
    const float* x    = (const float*)d_in[0];
    const float* We   = (const float*)d_in[1];
    const float* Ue   = (const float*)d_in[2];
    const float* be   = (const float*)d_in[3];
    const float* Wd   = (const float*)d_in[4];
    const float* Ud   = (const float*)d_in[5];
    const float* bd   = (const float*)d_in[6];
    const float* Wout = (const float*)d_in[7];
    const float* bout = (const float*)d_in[8];
    float* y = (float*)d_out;

    k_xz<<<8192, 128>>>(x, We, be);
    k_enc<<<512, 128>>>(Ue);
    k_dec<<<512, 128>>>(Ud, Wd, bd, Wout, bout, y);
}